// round 14
// baseline (speedup 1.0000x reference)
#include <cuda_runtime.h>
#include <cuda_fp16.h>
#include <cstdint>

// ---------------------------------------------------------------------------
// Problem constants
// ---------------------------------------------------------------------------
#define BB 512      // batch
#define SS 256      // set size
#define DD 64       // feature dim (K)
#define HH 64       // n_hidden_sets
#define EE 8        // n_elements
#define HE 512      // H*E (N of GEMM)
#define BN_EPS 1e-5f

#define NCTA 304          // 2 per SM on GB300 (152 SMs)
#define K1_THREADS 256

// smem layout (bytes) — Phase C US overlays [0, ~69K) after Phase B retires
#define S_BUF0 0                    // X fp16 whole-b buf 0 (32 KB)
#define S_BUF1 32768                // X fp16 whole-b buf 1 (32 KB)
#define S_RING 65536                // 2 x 16384 fp32 group staging (cp.async)
#define S_WFC  98304                // fc1_w transposed [h][j] (8 KB)
#define S_FB   106496               // fc1_b [32]
#define S_TSM  106624               // 2 x 64 floats (b-parity)
#define S_CTL  107136               // 8 ints: [0..3] ticket ring, [4] last flag
#define SM_TOTAL 107200

// ---------------------------------------------------------------------------
// Device scratch (no dynamic allocation allowed)
// ---------------------------------------------------------------------------
__device__ float g_u[BB * 32];      // fc1 output
__device__ int   g_ticket = 0;      // persistent work queue
__device__ int   g_done   = 0;      // CTA completion counter

__device__ __forceinline__ uint32_t smem_u32(const void* p) {
    uint32_t a;
    asm("{ .reg .u64 t; cvta.to.shared.u64 t, %1; cvt.u32.u64 %0, t; }" : "=r"(a) : "l"(p));
    return a;
}
__device__ __forceinline__ uint32_t swz(uint32_t off) {   // SW128: conflict-free ldmatrix
    return off ^ ((off >> 3) & 0x70);
}
__device__ __forceinline__ float lrelu(float x) { return fmaxf(x, 0.01f * x); }

__device__ __forceinline__ void ldsm_x4(uint32_t addr, uint32_t& r0, uint32_t& r1,
                                        uint32_t& r2, uint32_t& r3) {
    asm volatile("ldmatrix.sync.aligned.m8n8.x4.shared.b16 {%0,%1,%2,%3}, [%4];"
                 : "=r"(r0), "=r"(r1), "=r"(r2), "=r"(r3) : "r"(addr));
}
__device__ __forceinline__ void mma_fp16(float& c0, float& c1, float& c2, float& c3,
                                         uint32_t a0, uint32_t a1, uint32_t a2, uint32_t a3,
                                         uint32_t b0, uint32_t b1) {
    asm volatile("mma.sync.aligned.m16n8k16.row.col.f32.f16.f16.f32 "
                 "{%0,%1,%2,%3}, {%4,%5,%6,%7}, {%8,%9}, {%0,%1,%2,%3};"
                 : "+f"(c0), "+f"(c1), "+f"(c2), "+f"(c3)
                 : "r"(a0), "r"(a1), "r"(a2), "r"(a3), "r"(b0), "r"(b1));
}
#define CP_ASYNC16(saddr, gptr) \
    asm volatile("cp.async.ca.shared.global [%0], [%1], 16;" \
                 :: "r"(saddr), "l"(gptr) : "memory")
#define CP_COMMIT()  asm volatile("cp.async.commit_group;" ::: "memory")
#define CP_WAIT1()   asm volatile("cp.async.wait_group 1;" ::: "memory")
#define CP_WAIT0()   asm volatile("cp.async.wait_group 0;" ::: "memory")

__device__ __forceinline__ uint32_t pack_h2(float lo, float hi) {
    __half2 h = __floats2half2_rn(lo, hi);
    return *(uint32_t*)&h;
}

// cp.async one 16KB fp32 group (b, g) into a ring slot (per-thread: 4x16B)
__device__ __forceinline__ void issue_group(uint32_t ring_s, const float* __restrict__ X,
                                            int b, int g, int tid) {
    const float* gp = X + (size_t)b * (SS * DD) + g * 4096;
    #pragma unroll
    for (int j = 0; j < 4; j++) {
        int i = tid + j * 256;
        CP_ASYNC16(ring_s + i * 16, gp + i * 4);
    }
}

// convert one fp32 ring group -> swizzled fp16 at bufoff (8192-aligned)
// Each thread reads exactly the float4s it cp.async'd (self-consistent; no barrier).
__device__ __forceinline__ void cvt_group(char* smem, int ringoff, int bufoff, int tid) {
    #pragma unroll
    for (int j = 0; j < 4; j++) {
        int cc = tid + j * 256;            // float4 idx within 64-row group
        float4 v = *(const float4*)(smem + ringoff + cc * 16);
        int row = cc >> 4, k4 = (cc & 15) << 2;
        uint32_t sw = swz((uint32_t)row * 128u + (uint32_t)k4 * 2u);
        *(uint2*)(smem + bufoff + sw) =
            make_uint2(pack_h2(v.x, v.y), pack_h2(v.z, v.w));
    }
}

// ---------------------------------------------------------------------------
// Single persistent kernel: per-b tickets, whole-b fp16 double buffer,
// cp.async 2-slot fp32 ring feed, ONE barrier per b.
// ---------------------------------------------------------------------------
__global__ __launch_bounds__(K1_THREADS, 2)
void fused_all(const float* __restrict__ X, const float* __restrict__ Wc,
               const float* __restrict__ fc1_w, const float* __restrict__ fc1_b,
               const float* __restrict__ gamma, const float* __restrict__ beta,
               const float* __restrict__ fc2_w, const float* __restrict__ fc2_b,
               float* __restrict__ out) {
    extern __shared__ char smem[];
    const uint32_t sb = smem_u32(smem);
    const int tid  = threadIdx.x;
    const int hb   = tid >> 5;        // warp id == h-block
    const int lane = tid & 31;
    int* ctl = (int*)(smem + S_CTL);  // [0..3]=ticket ring, [4]=last flag
    const uint32_t ring0 = sb + S_RING, ring1 = sb + S_RING + 16384;

    // ===== Phase A: stage fc1 weights/bias; B fragments direct from Wc =====
    for (int i = tid; i < 32 * HH; i += K1_THREADS) {
        int j = i >> 6, h = i & 63;
        ((float*)(smem + S_WFC))[h * 32 + j] = fc1_w[i];
    }
    if (tid < 32) ((float*)(smem + S_FB))[tid] = fc1_b[tid];

    // PTX m16n8k16 .col B mapping (bit-exact verified R11-R13):
    // bf[e][2*ks]  : k = ks*16 + (lane%4)*2 + {0,1},  n = e*64 + hb*8 + lane/4
    // bf[e][2*ks+1]: same with k+8
    uint32_t bf[EE][8];
    {
        const int n  = hb * 8 + (lane >> 2);
        const int kb = (lane & 3) * 2;
        #pragma unroll
        for (int e = 0; e < EE; e++) {
            const float* wc_n = Wc + e * 64 + n;
            #pragma unroll
            for (int ks = 0; ks < 4; ks++) {
                int k0 = ks * 16 + kb;
                bf[e][2 * ks]     = pack_h2(__ldg(wc_n + (size_t)k0 * HE),
                                            __ldg(wc_n + (size_t)(k0 + 1) * HE));
                bf[e][2 * ks + 1] = pack_h2(__ldg(wc_n + (size_t)(k0 + 8) * HE),
                                            __ldg(wc_n + (size_t)(k0 + 9) * HE));
            }
        }
    }

    if (tid == 0) {
        ctl[0] = atomicAdd(&g_ticket, 1);
        ctl[1] = atomicAdd(&g_ticket, 1);
    }
    __syncthreads();

    // ===== Phase B =====
    int b  = ctl[0];
    int ti = 1;          // last-filled ticket slot
    int bi = 0;          // b parity

    // prime: stream whole b0 through the ring into BUF0, then start nb's g0
    if (b < BB) {
        issue_group(ring0, X, b, 0, tid); CP_COMMIT();
        issue_group(ring1, X, b, 1, tid); CP_COMMIT();
        CP_WAIT1(); cvt_group(smem, S_RING,         S_BUF0,          tid);
        issue_group(ring0, X, b, 2, tid); CP_COMMIT();
        CP_WAIT1(); cvt_group(smem, S_RING + 16384, S_BUF0 + 8192,   tid);
        issue_group(ring1, X, b, 3, tid); CP_COMMIT();
        CP_WAIT1(); cvt_group(smem, S_RING,         S_BUF0 + 16384,  tid);
        CP_WAIT0(); cvt_group(smem, S_RING + 16384, S_BUF0 + 24576,  tid);
        int nb0 = ctl[1];
        if (nb0 < BB) issue_group(ring0, X, nb0, 0, tid);
        CP_COMMIT();     // 1 pending group entering the loop
    }
    __syncthreads();

    while (b < BB) {
        const int nb = ctl[ti & 3];
        const int bufoff  = (bi & 1) ? S_BUF1 : S_BUF0;
        const int nbufoff = (bi & 1) ? S_BUF0 : S_BUF1;
        const bool have_next = (nb < BB);
        float sacc0 = 0.0f, sacc1 = 0.0f;

        #pragma unroll
        for (int g = 0; g < 4; g++) {
            if (g == 0 && tid == 0 && have_next)
                ctl[(ti + 1) & 3] = atomicAdd(&g_ticket, 1);

            // issue group g+1 of next b into ring[(g+1)&1]; always commit
            if (g < 3 && have_next)
                issue_group((g + 1) & 1 ? ring1 : ring0, X, nb, g + 1, tid);
            CP_COMMIT();
            CP_WAIT1();    // group g of next b now resident in ring[g&1]

            // convert group g of next b into the other fp16 buffer
            // (nbuf retired by previous end-of-b barrier; ring is per-thread)
            if (have_next)
                cvt_group(smem, S_RING + (g & 1) * 16384, nbufoff + g * 8192, tid);

            // ---- 4 m-tiles of current b (rows (4g+mq)*16 ..)
            #pragma unroll
            for (int mq = 0; mq < 4; mq++) {
                const int m0 = (g * 4 + mq) * 16;
                float c[EE][4];
                #pragma unroll
                for (int e = 0; e < EE; e++)
                    #pragma unroll
                    for (int i = 0; i < 4; i++) c[e][i] = 0.0f;

                #pragma unroll
                for (int ks = 0; ks < 4; ks++) {
                    uint32_t off = (uint32_t)(m0 + (lane & 15)) * 128u
                                 + (uint32_t)ks * 32u + (uint32_t)(lane >> 4) * 16u;
                    uint32_t sw = swz(off);
                    uint32_t a0, a1, a2, a3;
                    ldsm_x4(sb + bufoff + sw, a0, a1, a2, a3);
                    #pragma unroll
                    for (int e = 0; e < EE; e++)
                        mma_fp16(c[e][0], c[e][1], c[e][2], c[e][3],
                                 a0, a1, a2, a3, bf[e][2 * ks], bf[e][2 * ks + 1]);
                }

                // max over E first (lrelu monotone -> commutes exactly)
                float v0 = c[0][0], v1 = c[0][1], v2 = c[0][2], v3 = c[0][3];
                #pragma unroll
                for (int e = 1; e < EE; e++) {
                    v0 = fmaxf(v0, c[e][0]);
                    v1 = fmaxf(v1, c[e][1]);
                    v2 = fmaxf(v2, c[e][2]);
                    v3 = fmaxf(v3, c[e][3]);
                }
                sacc0 += lrelu(v0) + lrelu(v2);   // col h = hb*8 + (lane%4)*2
                sacc1 += lrelu(v1) + lrelu(v3);   // col h+1
            }
        }

        // ---- flush pooled sums into parity tsm, then the ONE barrier per b
        #pragma unroll
        for (int o = 4; o <= 16; o <<= 1) {
            sacc0 += __shfl_xor_sync(0xffffffffu, sacc0, o);
            sacc1 += __shfl_xor_sync(0xffffffffu, sacc1, o);
        }
        if (lane < 4) {
            float* tsm = (float*)(smem + S_TSM) + (bi & 1) * HH;
            tsm[hb * 8 + lane * 2]     = sacc0;
            tsm[hb * 8 + lane * 2 + 1] = sacc1;
        }
        __syncthreads();

        // start group 0 of the b after nb (ticket visible via the barrier)
        {
            int nb2 = ctl[(ti + 1) & 3];
            if (have_next && nb2 < BB) issue_group(ring0, X, nb2, 0, tid);
            CP_COMMIT();   // keep 1 pending group entering next iteration
        }

        // fc1 for b (warp 0 only; other warps proceed into next b's MMAs)
        if (tid < 32) {
            const float* tsm = (const float*)(smem + S_TSM) + (bi & 1) * HH;
            const float* wfc = (const float*)(smem + S_WFC);
            float uacc = ((const float*)(smem + S_FB))[tid];
            #pragma unroll 8
            for (int h = 0; h < HH; h++)
                uacc = fmaf(tsm[h], wfc[h * 32 + tid], uacc);
            g_u[b * 32 + tid] = uacc;
        }

        b = nb; ti++; bi++;
    }

    // ===== Phase C: last CTA runs BatchNorm + LeakyReLU + fc2 inline =====
    __threadfence();
    if (tid == 0) {
        int old = atomicAdd(&g_done, 1);
        ctl[4] = (old == NCTA - 1) ? 1 : 0;
    }
    __syncthreads();
    if (!ctl[4]) return;

    // stage g_u into padded smem US[b][j] stride 33 (Phase B region is dead)
    float* US = (float*)smem;
    for (int i = tid; i < BB * 32; i += K1_THREADS)
        US[(i >> 5) * 33 + (i & 31)] = g_u[i];
    float* PS   = US + BB * 33;                  // [8][32] partials
    float* MEAN = PS + 256;                      // [32]
    float* RS   = MEAN + 32;                     // [32]
    __syncthreads();

    const int j = tid & 31, g = tid >> 5;        // 8 groups x 32 features
    {
        float s = 0.0f;
        #pragma unroll 8
        for (int bb = g * 64; bb < g * 64 + 64; bb++) s += US[bb * 33 + j];
        PS[g * 32 + j] = s;
    }
    __syncthreads();
    if (tid < 32) {
        float m = 0.0f;
        #pragma unroll
        for (int g2 = 0; g2 < 8; g2++) m += PS[g2 * 32 + tid];
        MEAN[tid] = m * (1.0f / (float)BB);
    }
    __syncthreads();
    {
        float mu = MEAN[j], s = 0.0f;
        #pragma unroll 8
        for (int bb = g * 64; bb < g * 64 + 64; bb++) {
            float d = US[bb * 33 + j] - mu;
            s += d * d;
        }
        PS[g * 32 + j] = s;
    }
    __syncthreads();
    if (tid < 32) {
        float v = 0.0f;
        #pragma unroll
        for (int g2 = 0; g2 < 8; g2++) v += PS[g2 * 32 + tid];
        RS[tid] = rsqrtf(v * (1.0f / (float)BB) + BN_EPS);
    }
    __syncthreads();

    for (int bb = tid; bb < BB; bb += K1_THREADS) {
        float a = __ldg(&fc2_b[0]);
        #pragma unroll
        for (int j2 = 0; j2 < 32; j2++) {
            float y = (US[bb * 33 + j2] - MEAN[j2]) * RS[j2] * __ldg(&gamma[j2]) + __ldg(&beta[j2]);
            a = fmaf(lrelu(y), __ldg(&fc2_w[j2]), a);
        }
        out[bb] = a;
    }

    // reset counters for next graph replay
    if (tid == 0) { g_ticket = 0; g_done = 0; }
}

// ---------------------------------------------------------------------------
extern "C" void kernel_launch(void* const* d_in, const int* in_sizes, int n_in,
                              void* d_out, int out_size) {
    const float* X     = (const float*)d_in[0];
    const float* Wc    = (const float*)d_in[1];
    const float* fc1_w = (const float*)d_in[2];
    const float* fc1_b = (const float*)d_in[3];
    const float* gamma = (const float*)d_in[4];
    const float* beta  = (const float*)d_in[5];
    const float* fc2_w = (const float*)d_in[6];
    const float* fc2_b = (const float*)d_in[7];
    float* out = (float*)d_out;

    cudaFuncSetAttribute(fused_all, cudaFuncAttributeMaxDynamicSharedMemorySize, SM_TOTAL);
    fused_all<<<NCTA, K1_THREADS, SM_TOTAL>>>(X, Wc, fc1_w, fc1_b,
                                              gamma, beta, fc2_w, fc2_b, out);
}

// round 15
// speedup vs baseline: 1.4232x; 1.4232x over previous
#include <cuda_runtime.h>
#include <cuda_fp16.h>
#include <cstdint>

// ---------------------------------------------------------------------------
// Problem constants
// ---------------------------------------------------------------------------
#define BB 512      // batch
#define SS 256      // set size
#define DD 64       // feature dim (K)
#define HH 64       // n_hidden_sets
#define EE 8        // n_elements
#define HE 512      // H*E (N of GEMM)
#define BN_EPS 1e-5f

#define NCTA 128          // 1 CTA per SM (forced via smem); 512 = 128 x 4 exactly
#define K1_THREADS 256

// smem layout (bytes) — Phase C US overlays [0, ~69K) after Phase B retires
#define S_BUF0 0                    // X fp16 whole-b buf 0 (32 KB)
#define S_BUF1 32768                // X fp16 whole-b buf 1 (32 KB)
#define S_WFC  65536                // fc1_w transposed [h][j] (8 KB)
#define S_FB   73728                // fc1_b [32]
#define S_TSM  73856                // 2 x 64 floats (b-parity)
#define S_CTL  74368                // control ints
// Request 120 KB so 2 CTAs cannot co-reside on one SM (228 KB carveout cap).
#define SM_TOTAL 122880

// ---------------------------------------------------------------------------
// Device scratch (no dynamic allocation allowed)
// ---------------------------------------------------------------------------
__device__ float g_u[BB * 32];      // fc1 output
__device__ int   g_done = 0;        // CTA completion counter

__device__ __forceinline__ uint32_t smem_u32(const void* p) {
    uint32_t a;
    asm("{ .reg .u64 t; cvta.to.shared.u64 t, %1; cvt.u32.u64 %0, t; }" : "=r"(a) : "l"(p));
    return a;
}
__device__ __forceinline__ uint32_t swz(uint32_t off) {   // SW128: conflict-free ldmatrix
    return off ^ ((off >> 3) & 0x70);
}
__device__ __forceinline__ float lrelu(float x) { return fmaxf(x, 0.01f * x); }

__device__ __forceinline__ void ldsm_x4(uint32_t addr, uint32_t& r0, uint32_t& r1,
                                        uint32_t& r2, uint32_t& r3) {
    asm volatile("ldmatrix.sync.aligned.m8n8.x4.shared.b16 {%0,%1,%2,%3}, [%4];"
                 : "=r"(r0), "=r"(r1), "=r"(r2), "=r"(r3) : "r"(addr));
}
__device__ __forceinline__ void mma_fp16(float& c0, float& c1, float& c2, float& c3,
                                         uint32_t a0, uint32_t a1, uint32_t a2, uint32_t a3,
                                         uint32_t b0, uint32_t b1) {
    asm volatile("mma.sync.aligned.m16n8k16.row.col.f32.f16.f16.f32 "
                 "{%0,%1,%2,%3}, {%4,%5,%6,%7}, {%8,%9}, {%0,%1,%2,%3};"
                 : "+f"(c0), "+f"(c1), "+f"(c2), "+f"(c3)
                 : "r"(a0), "r"(a1), "r"(a2), "r"(a3), "r"(b0), "r"(b1));
}
__device__ __forceinline__ uint32_t pack_h2(float lo, float hi) {
    __half2 h = __floats2half2_rn(lo, hi);
    return *(uint32_t*)&h;
}

// convert 4 float4 (one 64-row group's share) -> swizzled fp16 at bufoff
// (bufoff is 8192-aligned, so base + swz(local) == swz(base + local))
__device__ __forceinline__ void cvt_sts_group(char* smem, int bufoff, int tid,
                                              const float4* v) {
    #pragma unroll
    for (int j = 0; j < 4; j++) {
        int cc = tid + j * 256;            // float4 idx within 64-row group
        int row = cc >> 4, k4 = (cc & 15) << 2;
        uint32_t sw = swz((uint32_t)row * 128u + (uint32_t)k4 * 2u);
        *(uint2*)(smem + bufoff + sw) =
            make_uint2(pack_h2(v[j].x, v[j].y), pack_h2(v[j].z, v[j].w));
    }
}

// ---------------------------------------------------------------------------
// Single persistent kernel: 1 CTA/SM, static 4-b schedule, whole-b double
// buffer, ONE 8-warp barrier per b, register-prefetch feed.
// ---------------------------------------------------------------------------
__global__ __launch_bounds__(K1_THREADS, 1)
void fused_all(const float* __restrict__ X, const float* __restrict__ Wc,
               const float* __restrict__ fc1_w, const float* __restrict__ fc1_b,
               const float* __restrict__ gamma, const float* __restrict__ beta,
               const float* __restrict__ fc2_w, const float* __restrict__ fc2_b,
               float* __restrict__ out) {
    extern __shared__ char smem[];
    const uint32_t sb = smem_u32(smem);
    const int tid  = threadIdx.x;
    const int hb   = tid >> 5;        // warp id == h-block
    const int lane = tid & 31;
    int* ctl = (int*)(smem + S_CTL);  // [0]=last-CTA flag

    // ===== Phase A: stage fc1 weights/bias; B fragments direct from Wc =====
    for (int i = tid; i < 32 * HH; i += K1_THREADS) {
        int j = i >> 6, h = i & 63;
        ((float*)(smem + S_WFC))[h * 32 + j] = fc1_w[i];
    }
    if (tid < 32) ((float*)(smem + S_FB))[tid] = fc1_b[tid];

    // PTX m16n8k16 .col B mapping (bit-exact verified R11-R14):
    // bf[e][2*ks]  : k = ks*16 + (lane%4)*2 + {0,1},  n = e*64 + hb*8 + lane/4
    // bf[e][2*ks+1]: same with k+8
    uint32_t bf[EE][8];
    {
        const int n  = hb * 8 + (lane >> 2);
        const int kb = (lane & 3) * 2;
        #pragma unroll
        for (int e = 0; e < EE; e++) {
            const float* wc_n = Wc + e * 64 + n;
            #pragma unroll
            for (int ks = 0; ks < 4; ks++) {
                int k0 = ks * 16 + kb;
                bf[e][2 * ks]     = pack_h2(__ldg(wc_n + (size_t)k0 * HE),
                                            __ldg(wc_n + (size_t)(k0 + 1) * HE));
                bf[e][2 * ks + 1] = pack_h2(__ldg(wc_n + (size_t)(k0 + 8) * HE),
                                            __ldg(wc_n + (size_t)(k0 + 9) * HE));
            }
        }
    }

    // ===== Phase B: static schedule b = cta + 128*i, i = 0..3 =====
    const float4* X4 = (const float4*)X;
    int b = blockIdx.x;

    // preload whole b0 into BUF0
    #pragma unroll
    for (int g = 0; g < 4; g++) {
        const float4* src = X4 + (size_t)b * 4096 + g * 1024;
        float4 v[4];
        #pragma unroll
        for (int j = 0; j < 4; j++) v[j] = src[tid + j * 256];
        cvt_sts_group(smem, S_BUF0 + g * 8192, tid, v);
    }
    __syncthreads();

    #pragma unroll 1
    for (int it = 0; it < 4; it++) {
        const int nb = b + NCTA;
        const bool have_next = (it < 3);
        const int bufoff  = (it & 1) ? S_BUF1 : S_BUF0;
        const int nbufoff = (it & 1) ? S_BUF0 : S_BUF1;
        float sacc0 = 0.0f, sacc1 = 0.0f;

        #pragma unroll
        for (int g = 0; g < 4; g++) {
            // ---- LDG group g of NEXT b (latency hidden behind 4 m-tiles)
            float4 v[4];
            if (have_next) {
                const float4* nsrc = X4 + (size_t)nb * 4096 + g * 1024;
                #pragma unroll
                for (int j = 0; j < 4; j++) v[j] = nsrc[tid + j * 256];
            }

            // ---- 4 m-tiles of current b (rows (4g+mq)*16 ..)
            #pragma unroll
            for (int mq = 0; mq < 4; mq++) {
                const int m0 = (g * 4 + mq) * 16;
                float c[EE][4];
                #pragma unroll
                for (int e = 0; e < EE; e++)
                    #pragma unroll
                    for (int i = 0; i < 4; i++) c[e][i] = 0.0f;

                #pragma unroll
                for (int ks = 0; ks < 4; ks++) {
                    uint32_t off = (uint32_t)(m0 + (lane & 15)) * 128u
                                 + (uint32_t)ks * 32u + (uint32_t)(lane >> 4) * 16u;
                    uint32_t sw = swz(off);
                    uint32_t a0, a1, a2, a3;
                    ldsm_x4(sb + bufoff + sw, a0, a1, a2, a3);
                    #pragma unroll
                    for (int e = 0; e < EE; e++)
                        mma_fp16(c[e][0], c[e][1], c[e][2], c[e][3],
                                 a0, a1, a2, a3, bf[e][2 * ks], bf[e][2 * ks + 1]);
                }

                // max over E first (lrelu monotone -> commutes exactly)
                float v0 = c[0][0], v1 = c[0][1], v2 = c[0][2], v3 = c[0][3];
                #pragma unroll
                for (int e = 1; e < EE; e++) {
                    v0 = fmaxf(v0, c[e][0]);
                    v1 = fmaxf(v1, c[e][1]);
                    v2 = fmaxf(v2, c[e][2]);
                    v3 = fmaxf(v3, c[e][3]);
                }
                sacc0 += lrelu(v0) + lrelu(v2);   // col h = hb*8 + (lane%4)*2
                sacc1 += lrelu(v1) + lrelu(v3);   // col h+1
            }

            // ---- convert + store group g of next b (nbuf retired by the
            //      previous end-of-b barrier; no extra sync needed)
            if (have_next) cvt_sts_group(smem, nbufoff + g * 8192, tid, v);
        }

        // ---- flush pooled sums into parity tsm, then the ONE barrier per b
        #pragma unroll
        for (int o = 4; o <= 16; o <<= 1) {
            sacc0 += __shfl_xor_sync(0xffffffffu, sacc0, o);
            sacc1 += __shfl_xor_sync(0xffffffffu, sacc1, o);
        }
        if (lane < 4) {
            float* tsm = (float*)(smem + S_TSM) + (it & 1) * HH;
            tsm[hb * 8 + lane * 2]     = sacc0;
            tsm[hb * 8 + lane * 2 + 1] = sacc1;
        }
        __syncthreads();

        // fc1 for b (warp 0 only; other warps proceed into next b's MMAs)
        if (tid < 32) {
            const float* tsm = (const float*)(smem + S_TSM) + (it & 1) * HH;
            const float* wfc = (const float*)(smem + S_WFC);
            float uacc = ((const float*)(smem + S_FB))[tid];
            #pragma unroll 8
            for (int h = 0; h < HH; h++)
                uacc = fmaf(tsm[h], wfc[h * 32 + tid], uacc);
            g_u[b * 32 + tid] = uacc;
        }

        b = nb;
    }

    // ===== Phase C: last CTA runs BatchNorm + LeakyReLU + fc2 inline =====
    __threadfence();
    if (tid == 0) {
        int old = atomicAdd(&g_done, 1);
        ctl[0] = (old == NCTA - 1) ? 1 : 0;
    }
    __syncthreads();
    if (!ctl[0]) return;

    // stage g_u into padded smem US[b][j] stride 33 (Phase B region is dead)
    float* US = (float*)smem;
    for (int i = tid; i < BB * 32; i += K1_THREADS)
        US[(i >> 5) * 33 + (i & 31)] = g_u[i];
    float* PS   = US + BB * 33;                  // [8][32] partials
    float* MEAN = PS + 256;                      // [32]
    float* RS   = MEAN + 32;                     // [32]
    __syncthreads();

    const int j = tid & 31, g = tid >> 5;        // 8 groups x 32 features
    {
        float s = 0.0f;
        #pragma unroll 8
        for (int bb = g * 64; bb < g * 64 + 64; bb++) s += US[bb * 33 + j];
        PS[g * 32 + j] = s;
    }
    __syncthreads();
    if (tid < 32) {
        float m = 0.0f;
        #pragma unroll
        for (int g2 = 0; g2 < 8; g2++) m += PS[g2 * 32 + tid];
        MEAN[tid] = m * (1.0f / (float)BB);
    }
    __syncthreads();
    {
        float mu = MEAN[j], s = 0.0f;
        #pragma unroll 8
        for (int bb = g * 64; bb < g * 64 + 64; bb++) {
            float d = US[bb * 33 + j] - mu;
            s += d * d;
        }
        PS[g * 32 + j] = s;
    }
    __syncthreads();
    if (tid < 32) {
        float v = 0.0f;
        #pragma unroll
        for (int g2 = 0; g2 < 8; g2++) v += PS[g2 * 32 + tid];
        RS[tid] = rsqrtf(v * (1.0f / (float)BB) + BN_EPS);
    }
    __syncthreads();

    for (int bb = tid; bb < BB; bb += K1_THREADS) {
        float a = __ldg(&fc2_b[0]);
        #pragma unroll
        for (int j2 = 0; j2 < 32; j2++) {
            float y = (US[bb * 33 + j2] - MEAN[j2]) * RS[j2] * __ldg(&gamma[j2]) + __ldg(&beta[j2]);
            a = fmaf(lrelu(y), __ldg(&fc2_w[j2]), a);
        }
        out[bb] = a;
    }

    // reset counter for next graph replay
    if (tid == 0) g_done = 0;
}

// ---------------------------------------------------------------------------
extern "C" void kernel_launch(void* const* d_in, const int* in_sizes, int n_in,
                              void* d_out, int out_size) {
    const float* X     = (const float*)d_in[0];
    const float* Wc    = (const float*)d_in[1];
    const float* fc1_w = (const float*)d_in[2];
    const float* fc1_b = (const float*)d_in[3];
    const float* gamma = (const float*)d_in[4];
    const float* beta  = (const float*)d_in[5];
    const float* fc2_w = (const float*)d_in[6];
    const float* fc2_b = (const float*)d_in[7];
    float* out = (float*)d_out;

    cudaFuncSetAttribute(fused_all, cudaFuncAttributeMaxDynamicSharedMemorySize, SM_TOTAL);
    fused_all<<<NCTA, K1_THREADS, SM_TOTAL>>>(X, Wc, fc1_w, fc1_b,
                                              gamma, beta, fc2_w, fc2_b, out);
}